// round 2
// baseline (speedup 1.0000x reference)
#include <cuda_runtime.h>
#include <math.h>

#define IMG_H 28
#define IMG_W 28
#define IMG_N 784
#define SWIN  11
#define SOUT  18        // 28-11+1
#define MAXB  65536

// accumulators: [q*64 + bank], q: 0=mse 1=ssim 2=Sa 3=Sb 4=Saa 5=Sbb 6=Sab
__device__ double   g_acc[7 * 64];
__device__ unsigned g_minenc, g_maxenc;
__device__ float    g_gw[SWIN];
__device__ float2   g_sob[(size_t)MAXB * IMG_N];   // (sobel_o, sobel_t) per pixel

// ---- float ordering encode/decode for atomic min/max ----
__device__ __forceinline__ unsigned encf(float f) {
    unsigned u = __float_as_uint(f);
    return (u & 0x80000000u) ? ~u : (u | 0x80000000u);
}
__device__ __forceinline__ float decf(unsigned e) {
    unsigned u = (e & 0x80000000u) ? (e & 0x7FFFFFFFu) : ~e;
    return __uint_as_float(u);
}

// ================= init =================
__global__ void k_init() {
    int t = threadIdx.x;
    for (int i = t; i < 7 * 64; i += blockDim.x) g_acc[i] = 0.0;
    if (t == 0) {
        g_minenc = 0xFFFFFFFFu;
        g_maxenc = 0u;
        double w[SWIN], s = 0.0;
        for (int i = 0; i < SWIN; i++) {
            double c = (double)i - (SWIN / 2);
            w[i] = exp(-(c * c) / (2.0 * 1.5 * 1.5));
            s += w[i];
        }
        for (int i = 0; i < SWIN; i++) g_gw[i] = (float)(w[i] / s);
    }
}

// ================= min/max of target =================
__global__ void k_minmax(const float4* __restrict__ t, int n4) {
    float lo = 3.402823466e38f, hi = -3.402823466e38f;
    for (int i = blockIdx.x * blockDim.x + threadIdx.x; i < n4;
         i += gridDim.x * blockDim.x) {
        float4 x = t[i];
        lo = fminf(lo, fminf(fminf(x.x, x.y), fminf(x.z, x.w)));
        hi = fmaxf(hi, fmaxf(fmaxf(x.x, x.y), fmaxf(x.z, x.w)));
    }
#pragma unroll
    for (int o = 16; o; o >>= 1) {
        lo = fminf(lo, __shfl_down_sync(0xFFFFFFFFu, lo, o));
        hi = fmaxf(hi, __shfl_down_sync(0xFFFFFFFFu, hi, o));
    }
    if ((threadIdx.x & 31) == 0) {
        atomicMin(&g_minenc, encf(lo));
        atomicMax(&g_maxenc, encf(hi));
    }
}

// ================= per-image: MSE + SSIM + sobel g =================
__global__ __launch_bounds__(128) void k_img(const float4* __restrict__ o4,
                                             const float4* __restrict__ t4) {
    __shared__ float2 uv[IMG_N];            // (u=o+t, v=o-t)
    __shared__ float2 pq[IMG_N];            // (u*u, v*v)
    __shared__ float2 Huv[IMG_H * SOUT];    // horiz-filtered (U,V), 28x18
    __shared__ float2 Hpq[IMG_H * SOUT];    // horiz-filtered (P,Q)
    __shared__ float  wsum1[4], wsum2[4];

    const int b = blockIdx.x;
    const int tid = threadIdx.x;

    float gw[SWIN];
#pragma unroll
    for (int k = 0; k < SWIN; k++) gw[k] = g_gw[k];

    // ---- load + prep + mse partial ----
    float msep = 0.0f;
    const float4* ob = o4 + (size_t)b * (IMG_N / 4);
    const float4* tb = t4 + (size_t)b * (IMG_N / 4);
    for (int i = tid; i < IMG_N / 4; i += 128) {
        float4 a = ob[i], c = tb[i];
        int base = i * 4;
        float u0 = a.x + c.x, v0 = a.x - c.x;
        float u1 = a.y + c.y, v1 = a.y - c.y;
        float u2 = a.z + c.z, v2 = a.z - c.z;
        float u3 = a.w + c.w, v3 = a.w - c.w;
        uv[base + 0] = make_float2(u0, v0);
        uv[base + 1] = make_float2(u1, v1);
        uv[base + 2] = make_float2(u2, v2);
        uv[base + 3] = make_float2(u3, v3);
        pq[base + 0] = make_float2(u0 * u0, v0 * v0);
        pq[base + 1] = make_float2(u1 * u1, v1 * v1);
        pq[base + 2] = make_float2(u2 * u2, v2 * v2);
        pq[base + 3] = make_float2(u3 * u3, v3 * v3);
        msep += v0 * v0 + v1 * v1 + v2 * v2 + v3 * v3;
    }
    __syncthreads();

    // ---- horizontal Gaussian (28 rows x 3 segs of 6 outputs, sliding window) ----
    if (tid < 84) {
        int r = tid / 3, sg = tid - 3 * (tid / 3);
        int j = sg * 6;
        const float2* row  = uv + r * IMG_W;
        const float2* rowp = pq + r * IMG_W;
        float2 wu[SWIN], wp[SWIN];
#pragma unroll
        for (int k = 0; k < SWIN; k++) { wu[k] = row[j + k]; wp[k] = rowp[j + k]; }
#pragma unroll
        for (int oi = 0; oi < 6; oi++) {
            float Ux = 0.f, Uy = 0.f, Px = 0.f, Py = 0.f;
#pragma unroll
            for (int k = 0; k < SWIN; k++) {
                Ux = fmaf(gw[k], wu[k].x, Ux);
                Uy = fmaf(gw[k], wu[k].y, Uy);
                Px = fmaf(gw[k], wp[k].x, Px);
                Py = fmaf(gw[k], wp[k].y, Py);
            }
            Huv[r * SOUT + j + oi] = make_float2(Ux, Uy);
            Hpq[r * SOUT + j + oi] = make_float2(Px, Py);
            if (oi < 5) {
#pragma unroll
                for (int k = 0; k < SWIN - 1; k++) { wu[k] = wu[k + 1]; wp[k] = wp[k + 1]; }
                wu[SWIN - 1] = row[j + oi + SWIN];
                wp[SWIN - 1] = rowp[j + oi + SWIN];
            }
        }
    }
    __syncthreads();

    // ---- vertical Gaussian + SSIM map (18 cols x 3 segs of 6 rows) ----
    float ssimp = 0.0f;
    if (tid < 54) {
        int cc = tid / 3, sg = tid - 3 * (tid / 3);
        int j = sg * 6;
        float R  = decf(g_maxenc) - decf(g_minenc);
        float C1 = (0.01f * R) * (0.01f * R);
        float C2 = (0.03f * R) * (0.03f * R);
        float2 wu[SWIN], wp[SWIN];
#pragma unroll
        for (int k = 0; k < SWIN; k++) {
            wu[k] = Huv[(j + k) * SOUT + cc];
            wp[k] = Hpq[(j + k) * SOUT + cc];
        }
#pragma unroll
        for (int oi = 0; oi < 6; oi++) {
            float U = 0.f, V = 0.f, P = 0.f, Q = 0.f;
#pragma unroll
            for (int k = 0; k < SWIN; k++) {
                U = fmaf(gw[k], wu[k].x, U);
                V = fmaf(gw[k], wu[k].y, V);
                P = fmaf(gw[k], wp[k].x, P);
                Q = fmaf(gw[k], wp[k].y, Q);
            }
            float A = U * U, Bv = V * V;
            float num1 = 0.5f * (A - Bv) + C1;            // 2*mu1mu2 + C1
            float den1 = 0.5f * (A + Bv) + C1;            // mu1^2+mu2^2 + C1
            float num2 = 0.5f * (P - Q - A + Bv) + C2;    // 2*s12 + C2
            float den2 = 0.5f * (P + Q - A - Bv) + C2;    // s1+s2 + C2
            ssimp += __fdividef(num1 * num2, den1 * den2);
            if (oi < 5) {
#pragma unroll
                for (int k = 0; k < SWIN - 1; k++) { wu[k] = wu[k + 1]; wp[k] = wp[k + 1]; }
                wu[SWIN - 1] = Huv[(j + oi + SWIN) * SOUT + cc];
                wp[SWIN - 1] = Hpq[(j + oi + SWIN) * SOUT + cc];
            }
        }
    }

    // ---- per-image sobel g (derivW + [1,2,1] rows + x4 channel), from u,v ----
    // o = (u+v)/2, t = (u-v)/2 -> g_o = 2*(smu+smv), g_t = 2*(smu-smv)
    for (int idx = tid; idx < IMG_N; idx += 128) {
        int r = idx / IMG_W;
        int c = idx - r * IMG_W;
        int cp = (c < IMG_W - 1) ? c + 1 : IMG_W - 1;
        int cm = (c > 0) ? c - 1 : 0;
        int rm = (r > 0) ? r - 1 : 0;
        int rp = (r < IMG_H - 1) ? r + 1 : IMG_H - 1;
        // derivW at rows rm, r, rp (clamped indices reproduce symmetric pad)
        float2 a0 = uv[rm * IMG_W + cp], b0 = uv[rm * IMG_W + cm];
        float2 a1 = uv[r  * IMG_W + cp], b1 = uv[r  * IMG_W + cm];
        float2 a2 = uv[rp * IMG_W + cp], b2 = uv[rp * IMG_W + cm];
        float smu = (a0.x - b0.x) + 2.f * (a1.x - b1.x) + (a2.x - b2.x);
        float smv = (a0.y - b0.y) + 2.f * (a1.y - b1.y) + (a2.y - b2.y);
        float go = 2.f * (smu + smv);
        float gt = 2.f * (smu - smv);
        g_sob[(size_t)b * IMG_N + idx] = make_float2(go, gt);
    }

    // ---- block reduce mse + ssim, one banked atomic each ----
    float s1 = msep, s2 = ssimp;
#pragma unroll
    for (int o = 16; o; o >>= 1) {
        s1 += __shfl_down_sync(0xFFFFFFFFu, s1, o);
        s2 += __shfl_down_sync(0xFFFFFFFFu, s2, o);
    }
    int wid = tid >> 5;
    if ((tid & 31) == 0) { wsum1[wid] = s1; wsum2[wid] = s2; }
    __syncthreads();
    if (tid == 0) {
        float m = wsum1[0] + wsum1[1] + wsum1[2] + wsum1[3];
        float s = wsum2[0] + wsum2[1] + wsum2[2] + wsum2[3];
        atomicAdd(&g_acc[0 * 64 + (b & 63)], (double)m);
        atomicAdd(&g_acc[1 * 64 + (b & 63)], (double)s);
    }
}

// ================= batch-axis sobel smoothing + Pearson sums =================
__global__ __launch_bounds__(800) void k_pear(int B) {
    const int p  = threadIdx.x;       // pixel id (only < 784 active for loads)
    const int b0 = blockIdx.x * 64;
    float Sa = 0.f, Sb = 0.f, Saa = 0.f, Sbb = 0.f, Sab = 0.f;
    if (p < IMG_N) {
        int bm = (b0 > 0) ? b0 - 1 : 0;
        float2 gm = g_sob[(size_t)bm * IMG_N + p];
        float2 gc = g_sob[(size_t)b0 * IMG_N + p];
#pragma unroll 4
        for (int i = 0; i < 64; i++) {
            int bcur = b0 + i;
            int bn = (bcur + 1 < B) ? bcur + 1 : B - 1;
            float2 gp = g_sob[(size_t)bn * IMG_N + p];
            float sa = gm.x + 2.f * gc.x + gp.x;
            float sb = gm.y + 2.f * gc.y + gp.y;
            Sa += sa; Sb += sb;
            Saa = fmaf(sa, sa, Saa);
            Sbb = fmaf(sb, sb, Sbb);
            Sab = fmaf(sa, sb, Sab);
            gm = gc; gc = gp;
        }
    }
    // reduce across 800 threads (25 full warps)
    __shared__ float red[25][5];
#pragma unroll
    for (int o = 16; o; o >>= 1) {
        Sa  += __shfl_down_sync(0xFFFFFFFFu, Sa, o);
        Sb  += __shfl_down_sync(0xFFFFFFFFu, Sb, o);
        Saa += __shfl_down_sync(0xFFFFFFFFu, Saa, o);
        Sbb += __shfl_down_sync(0xFFFFFFFFu, Sbb, o);
        Sab += __shfl_down_sync(0xFFFFFFFFu, Sab, o);
    }
    int wid = p >> 5;
    if ((p & 31) == 0) {
        red[wid][0] = Sa; red[wid][1] = Sb; red[wid][2] = Saa;
        red[wid][3] = Sbb; red[wid][4] = Sab;
    }
    __syncthreads();
    if (p == 0) {
        double a = 0, bq = 0, aa = 0, bb = 0, ab = 0;
        for (int w = 0; w < 25; w++) {
            a += red[w][0]; bq += red[w][1]; aa += red[w][2];
            bb += red[w][3]; ab += red[w][4];
        }
        int bank = blockIdx.x & 63;
        atomicAdd(&g_acc[2 * 64 + bank], a);
        atomicAdd(&g_acc[3 * 64 + bank], bq);
        atomicAdd(&g_acc[4 * 64 + bank], aa);
        atomicAdd(&g_acc[5 * 64 + bank], bb);
        atomicAdd(&g_acc[6 * 64 + bank], ab);
    }
}

// ================= finalize =================
__global__ void k_final(float* out, int out_size, int B) {
    if (threadIdx.x != 0 || blockIdx.x != 0) return;
    double q[7];
    for (int i = 0; i < 7; i++) {
        double s = 0;
        for (int k = 0; k < 64; k++) s += g_acc[i * 64 + k];
        q[i] = s;
    }
    double N    = (double)B * (double)IMG_N;
    double mse  = q[0] / N;
    double ssim = q[1] / ((double)B * (double)(SOUT * SOUT));
    double psnr = 10.0 * log10(1.0 / mse);
    double Sa = q[2], Sb = q[3], Saa = q[4], Sbb = q[5], Sab = q[6];
    double num = Sab - Sa * Sb / N;
    double den = sqrt((Saa - Sa * Sa / N) * (Sbb - Sb * Sb / N));
    double epi = num / den;
    double loss = 1.0 * mse + 0.5 * (1.0 - ssim) + 0.1 * epi + 0.01 * psnr;
    for (int i = 0; i < out_size; i++) out[i] = (float)loss;
}

// ================= launcher =================
extern "C" void kernel_launch(void* const* d_in, const int* in_sizes, int n_in,
                              void* d_out, int out_size) {
    const float4* o4 = (const float4*)d_in[0];  // "output"
    const float4* t4 = (const float4*)d_in[1];  // "target"
    int n = in_sizes[0];
    int B = n / IMG_N;           // 65536

    k_init<<<1, 128>>>();
    k_minmax<<<1024, 256>>>(t4, n / 4);
    k_img<<<B, 128>>>(o4, t4);
    k_pear<<<B / 64, 800>>>(B);
    k_final<<<1, 1>>>((float*)d_out, out_size, B);
}

// round 3
// speedup vs baseline: 1.2463x; 1.2463x over previous
#include <cuda_runtime.h>
#include <math.h>

#define IMG_H 28
#define IMG_W 28
#define IMG_N 784
#define SWIN  11
#define SOUT  18        // 28-11+1
#define C_IMG 16        // images per block (chunk)

typedef unsigned long long u64;

// accumulators: [q*64 + bank], q: 0=mse 1=ssim 2=Sa 3=Sb 4=Saa 5=Sbb 6=Sab
__device__ double   g_acc[7 * 64];
__device__ unsigned g_minenc, g_maxenc;
__device__ float    g_gw[SWIN];

// ---- float ordering encode/decode for atomic min/max ----
__device__ __forceinline__ unsigned encf(float f) {
    unsigned u = __float_as_uint(f);
    return (u & 0x80000000u) ? ~u : (u | 0x80000000u);
}
__device__ __forceinline__ float decf(unsigned e) {
    unsigned u = (e & 0x80000000u) ? (e & 0x7FFFFFFFu) : ~e;
    return __uint_as_float(u);
}

// ---- packed f32x2 helpers ----
__device__ __forceinline__ u64 pack2(float x, float y) {
    u64 r;
    asm("mov.b64 %0, {%1, %2};" : "=l"(r) : "r"(__float_as_uint(x)), "r"(__float_as_uint(y)));
    return r;
}
__device__ __forceinline__ void unpack2(u64 v, float &x, float &y) {
    unsigned a, b;
    asm("mov.b64 {%0, %1}, %2;" : "=r"(a), "=r"(b) : "l"(v));
    x = __uint_as_float(a);
    y = __uint_as_float(b);
}
__device__ __forceinline__ u64 fma2(u64 a, u64 b, u64 c) {   // a*b + c
    u64 d;
    asm("fma.rn.f32x2 %0, %1, %2, %3;" : "=l"(d) : "l"(a), "l"(b), "l"(c));
    return d;
}
__device__ __forceinline__ u64 add2(u64 a, u64 b) {
    u64 d;
    asm("add.rn.f32x2 %0, %1, %2;" : "=l"(d) : "l"(a), "l"(b));
    return d;
}

// ================= init =================
__global__ void k_init() {
    int t = threadIdx.x;
    for (int i = t; i < 7 * 64; i += blockDim.x) g_acc[i] = 0.0;
    if (t == 0) {
        g_minenc = 0xFFFFFFFFu;
        g_maxenc = 0u;
        double w[SWIN], s = 0.0;
        for (int i = 0; i < SWIN; i++) {
            double c = (double)i - (SWIN / 2);
            w[i] = exp(-(c * c) / (2.0 * 1.5 * 1.5));
            s += w[i];
        }
        for (int i = 0; i < SWIN; i++) g_gw[i] = (float)(w[i] / s);
    }
}

// ================= min/max of target =================
__global__ void k_minmax(const float4* __restrict__ t, int n4) {
    float lo = 3.402823466e38f, hi = -3.402823466e38f;
    for (int i = blockIdx.x * blockDim.x + threadIdx.x; i < n4;
         i += gridDim.x * blockDim.x) {
        float4 x = t[i];
        lo = fminf(lo, fminf(fminf(x.x, x.y), fminf(x.z, x.w)));
        hi = fmaxf(hi, fmaxf(fmaxf(x.x, x.y), fmaxf(x.z, x.w)));
    }
#pragma unroll
    for (int o = 16; o; o >>= 1) {
        lo = fminf(lo, __shfl_down_sync(0xFFFFFFFFu, lo, o));
        hi = fmaxf(hi, __shfl_down_sync(0xFFFFFFFFu, hi, o));
    }
    if ((threadIdx.x & 31) == 0) {
        atomicMin(&g_minenc, encf(lo));
        atomicMax(&g_maxenc, encf(hi));
    }
}

// ========== fused: MSE + SSIM + sobel + batch-smooth + Pearson ==========
__global__ __launch_bounds__(256) void k_fused(const float4* __restrict__ o4,
                                               const float4* __restrict__ t4,
                                               int B) {
    __shared__ u64 uv[IMG_N];            // (u=o+t, v=o-t) packed
    __shared__ u64 pq[IMG_N];            // (u*u, v*v) packed
    __shared__ u64 Huv[IMG_H * SOUT];    // horiz-filtered (U,V)
    __shared__ u64 Hpq[IMG_H * SOUT];    // horiz-filtered (P,Q)
    __shared__ u64 gsm[IMG_N];           // sobel (smu, smv) of current image
    __shared__ float red[8][7];

    const int tid = threadIdx.x;
    const int c0 = blockIdx.x * C_IMG;

    // packed Gaussian weights (w,w)
    u64 ww[SWIN];
#pragma unroll
    for (int k = 0; k < SWIN; k++) { float w = g_gw[k]; ww[k] = pack2(w, w); }
    const u64 TWO2 = pack2(2.0f, 2.0f);
    const u64 NEG2 = pack2(-1.0f, -1.0f);

    float R  = decf(g_maxenc) - decf(g_minenc);
    float C1 = (0.01f * R) * (0.01f * R);
    float C2 = (0.03f * R) * (0.03f * R);

    // per-thread accumulators
    float msep = 0.f, ssimp = 0.f;
    float Sa = 0.f, Sb = 0.f, Saa = 0.f, Sbb = 0.f, Sab = 0.f;

    // Pearson batch-recurrence registers: pixels p = tid + 256*k
    u64 gm[4], gc[4];
#pragma unroll
    for (int k = 0; k < 4; k++) { gm[k] = 0; gc[k] = 0; }

    for (int ii = -1; ii <= C_IMG; ii++) {
        int b = c0 + ii;
        int bc = b < 0 ? 0 : (b >= B ? B - 1 : b);
        bool interior = (ii >= 0) && (ii < C_IMG);

        // ---------- phase A: load image bc, build uv (+pq, mse if interior)
        {
            const float4* ob = o4 + (size_t)bc * (IMG_N / 4);
            const float4* tb = t4 + (size_t)bc * (IMG_N / 4);
            if (tid < IMG_N / 4) {
                float4 a = ob[tid], c = tb[tid];
                float u0 = a.x + c.x, v0 = a.x - c.x;
                float u1 = a.y + c.y, v1 = a.y - c.y;
                float u2 = a.z + c.z, v2 = a.z - c.z;
                float u3 = a.w + c.w, v3 = a.w - c.w;
                int base = tid * 4;
                uv[base + 0] = pack2(u0, v0);
                uv[base + 1] = pack2(u1, v1);
                uv[base + 2] = pack2(u2, v2);
                uv[base + 3] = pack2(u3, v3);
                if (interior) {
                    pq[base + 0] = pack2(u0 * u0, v0 * v0);
                    pq[base + 1] = pack2(u1 * u1, v1 * v1);
                    pq[base + 2] = pack2(u2 * u2, v2 * v2);
                    pq[base + 3] = pack2(u3 * u3, v3 * v3);
                    msep += v0 * v0 + v1 * v1 + v2 * v2 + v3 * v3;
                }
            }
        }
        __syncthreads();

        // ---------- phase B: sobel (threads 0..55) + horiz conv (64..147, interior)
        if (tid < 56) {
            int c = tid >> 1, s = tid & 1;
            int cp = (c < IMG_W - 1) ? c + 1 : IMG_W - 1;
            int cm = (c > 0) ? c - 1 : 0;
            int r0 = s * 14;
            int rm0 = (r0 > 0) ? r0 - 1 : 0;
            // d(r) = uv[r][cp] - uv[r][cm], packed
            u64 dm = fma2(NEG2, uv[rm0 * IMG_W + cm], uv[rm0 * IMG_W + cp]);
            u64 dc = fma2(NEG2, uv[r0 * IMG_W + cm], uv[r0 * IMG_W + cp]);
#pragma unroll
            for (int rr = 0; rr < 14; rr++) {
                int r = r0 + rr;
                int rp = (r < IMG_H - 1) ? r + 1 : IMG_H - 1;
                u64 dp = fma2(NEG2, uv[rp * IMG_W + cm], uv[rp * IMG_W + cp]);
                u64 t = add2(dm, dp);
                t = fma2(TWO2, dc, t);
                gsm[r * IMG_W + c] = t;      // (smu, smv)
                dm = dc; dc = dp;
            }
        } else if (interior && tid >= 64 && tid < 64 + 84) {
            int h = tid - 64;
            int r = h / 3, s = h - 3 * r;
            int ibase = r * IMG_W + s * 6;
            u64 au[6], ap[6];
#pragma unroll
            for (int oi = 0; oi < 6; oi++) { au[oi] = 0; ap[oi] = 0; }
#pragma unroll
            for (int t = 0; t < 16; t++) {
                u64 xu = uv[ibase + t];
                u64 xp = pq[ibase + t];
#pragma unroll
                for (int oi = 0; oi < 6; oi++) {
                    int k = t - oi;
                    if (k >= 0 && k < SWIN) {
                        au[oi] = fma2(ww[k], xu, au[oi]);
                        ap[oi] = fma2(ww[k], xp, ap[oi]);
                    }
                }
            }
            int obase = r * SOUT + s * 6;
#pragma unroll
            for (int oi = 0; oi < 6; oi++) {
                Huv[obase + oi] = au[oi];
                Hpq[obase + oi] = ap[oi];
            }
        }
        __syncthreads();

        // ---------- phase C: vertical conv + SSIM (interior, tid<54); Pearson (all)
        if (interior && tid < 54) {
            int cc = tid / 3, s = tid - 3 * (tid / 3);
            int j0 = s * 6;
            u64 au[6], ap[6];
#pragma unroll
            for (int oi = 0; oi < 6; oi++) { au[oi] = 0; ap[oi] = 0; }
#pragma unroll
            for (int t = 0; t < 16; t++) {
                u64 xu = Huv[(j0 + t) * SOUT + cc];
                u64 xp = Hpq[(j0 + t) * SOUT + cc];
#pragma unroll
                for (int oi = 0; oi < 6; oi++) {
                    int k = t - oi;
                    if (k >= 0 && k < SWIN) {
                        au[oi] = fma2(ww[k], xu, au[oi]);
                        ap[oi] = fma2(ww[k], xp, ap[oi]);
                    }
                }
            }
#pragma unroll
            for (int oi = 0; oi < 6; oi++) {
                float U, V, P, Q;
                unpack2(au[oi], U, V);
                unpack2(ap[oi], P, Q);
                float A = U * U, Bv = V * V;
                float num1 = 0.5f * (A - Bv) + C1;           // 2*mu1mu2 + C1
                float den1 = 0.5f * (A + Bv) + C1;           // mu1^2+mu2^2 + C1
                float num2 = 0.5f * (P - Q - A + Bv) + C2;   // 2*s12 + C2
                float den2 = 0.5f * (P + Q - A - Bv) + C2;   // s1+s2 + C2
                ssimp += __fdividef(num1 * num2, den1 * den2);
            }
        }

        // Pearson batch recurrence: s[jp] = g[jp-1] + 2 g[jp] + g[jp+1], jp = ii-1
#pragma unroll
        for (int k = 0; k < 4; k++) {
            int p = tid + k * 256;
            if (p < IMG_N) {
                u64 gn = gsm[p];
                if (ii >= 1) {
                    u64 t = add2(gm[k], gn);
                    t = fma2(TWO2, gc[k], t);
                    float su, sv;
                    unpack2(t, su, sv);
                    float sa = su + sv, sb = su - sv;   // scale factors cancel in pearson
                    Sa += sa; Sb += sb;
                    Saa = fmaf(sa, sa, Saa);
                    Sbb = fmaf(sb, sb, Sbb);
                    Sab = fmaf(sa, sb, Sab);
                }
                gm[k] = gc[k]; gc[k] = gn;
            }
        }
        // no sync needed here: next phase A touches only uv/pq (disjoint from
        // phase-C reads), and the sync after A orders gsm/Huv rewrites.
    }

    // ---------- block reduction: 7 sums ----------
    float v0 = msep, v1 = ssimp, v2 = Sa, v3 = Sb, v4 = Saa, v5 = Sbb, v6 = Sab;
#pragma unroll
    for (int o = 16; o; o >>= 1) {
        v0 += __shfl_down_sync(0xFFFFFFFFu, v0, o);
        v1 += __shfl_down_sync(0xFFFFFFFFu, v1, o);
        v2 += __shfl_down_sync(0xFFFFFFFFu, v2, o);
        v3 += __shfl_down_sync(0xFFFFFFFFu, v3, o);
        v4 += __shfl_down_sync(0xFFFFFFFFu, v4, o);
        v5 += __shfl_down_sync(0xFFFFFFFFu, v5, o);
        v6 += __shfl_down_sync(0xFFFFFFFFu, v6, o);
    }
    int wid = tid >> 5;
    if ((tid & 31) == 0) {
        red[wid][0] = v0; red[wid][1] = v1; red[wid][2] = v2; red[wid][3] = v3;
        red[wid][4] = v4; red[wid][5] = v5; red[wid][6] = v6;
    }
    __syncthreads();
    if (tid < 7) {
        double s = 0;
        for (int w = 0; w < 8; w++) s += (double)red[w][tid];
        atomicAdd(&g_acc[tid * 64 + (blockIdx.x & 63)], s);
    }
}

// ================= finalize =================
__global__ void k_final(float* out, int out_size, int B) {
    if (threadIdx.x != 0 || blockIdx.x != 0) return;
    double q[7];
    for (int i = 0; i < 7; i++) {
        double s = 0;
        for (int k = 0; k < 64; k++) s += g_acc[i * 64 + k];
        q[i] = s;
    }
    double N    = (double)B * (double)IMG_N;
    double mse  = q[0] / N;
    double ssim = q[1] / ((double)B * (double)(SOUT * SOUT));
    double psnr = 10.0 * log10(1.0 / mse);
    double Sa = q[2], Sb = q[3], Saa = q[4], Sbb = q[5], Sab = q[6];
    double num = Sab - Sa * Sb / N;
    double den = sqrt((Saa - Sa * Sa / N) * (Sbb - Sb * Sb / N));
    double epi = num / den;
    double loss = 1.0 * mse + 0.5 * (1.0 - ssim) + 0.1 * epi + 0.01 * psnr;
    for (int i = 0; i < out_size; i++) out[i] = (float)loss;
}

// ================= launcher =================
extern "C" void kernel_launch(void* const* d_in, const int* in_sizes, int n_in,
                              void* d_out, int out_size) {
    const float4* o4 = (const float4*)d_in[0];  // "output"
    const float4* t4 = (const float4*)d_in[1];  // "target"
    int n = in_sizes[0];
    int B = n / IMG_N;           // 65536

    k_init<<<1, 128>>>();
    k_minmax<<<1024, 256>>>(t4, n / 4);
    k_fused<<<B / C_IMG, 256>>>(o4, t4, B);
    k_final<<<1, 1>>>((float*)d_out, out_size, B);
}